// round 12
// baseline (speedup 1.0000x reference)
#include <cuda_runtime.h>
#include <cstdint>
#include <cstddef>

#define NN    50000
#define BB    64
#define DD    16
#define NDRVN 1000
#define MAXACT (NDRVN * DD)

typedef unsigned long long u64;

struct Params { const float* w[7]; const float* b[7]; };

// Scratch (static device arrays are the sanctioned workaround)
__device__ float g_bufA[(size_t)NN * BB];
__device__ float g_bufB[(size_t)NN * BB];
__device__ unsigned char g_flags[NN];
__device__ int g_list[MAXACT];
__device__ int g_cnt;

// ---------------- packed f32x2 primitives (Blackwell FFMA2 path) ----------------
__device__ __forceinline__ u64 fma2(u64 a, u64 b, u64 c) {
    u64 d;
    asm("fma.rn.f32x2 %0, %1, %2, %3;" : "=l"(d) : "l"(a), "l"(b), "l"(c));
    return d;
}
__device__ __forceinline__ u64 add2(u64 a, u64 b) {
    u64 d;
    asm("add.rn.f32x2 %0, %1, %2;" : "=l"(d) : "l"(a), "l"(b));
    return d;
}
__device__ __forceinline__ u64 mul2(u64 a, u64 b) {
    u64 d;
    asm("mul.rn.f32x2 %0, %1, %2;" : "=l"(d) : "l"(a), "l"(b));
    return d;
}
__device__ __forceinline__ u64 relu2(u64 x) {
    u64 r;
    asm("{\n\t"
        ".reg .f32 lo, hi;\n\t"
        "mov.b64 {lo, hi}, %1;\n\t"
        "max.f32 lo, lo, 0f00000000;\n\t"
        "max.f32 hi, hi, 0f00000000;\n\t"
        "mov.b64 %0, {lo, hi};\n\t"
        "}" : "=l"(r) : "l"(x));
    return r;
}

// ---------------- shared weights: duplicated (w,w) pairs, bias folded in ----------------
// s_w[l][co][q] as ulonglong2 (LDS.128 = 2 weight-pairs). Row of 16 duplicated floats:
//   layers 1..6: slots 0..14 = weights (ci*3+k), slot 15 = bias
//   layer  0   : slots 0..2  = weights, slot 3 = bias
__device__ __forceinline__ void load_weights(const Params& p, ulonglong2 (*sw)[5][8]) {
    float2* fp = (float2*)sw;
    for (int e = threadIdx.x; e < 7 * 5 * 16; e += blockDim.x) {
        int l = e / 80;
        int r = e % 80;
        int co = r / 16;
        int j  = r % 16;
        int nci   = (l == 0) ? 1 : 5;
        int nco   = (l == 6) ? 1 : 5;
        int nw    = nci * 3;
        int bslot = (l == 0) ? 3 : 15;
        float v = 0.0f;
        if (co < nco) {
            if (j < nw)          v = p.w[l][co * nw + j];
            else if (j == bslot) v = p.b[l][co];
        }
        fp[e] = make_float2(v, v);
    }
    __syncthreads();
}

// ---------------- layer-major streaming conv: one node per warp, batch-pair per lane ----
// Register-resident sequence processed layer-by-layer in place; weights register-cached
// per (layer, co, phase) and reused across a 3-wide t-chunk. Last co of each layer is
// written in place (s[co] is read only in phase 1, written in phase 2, and later chunks
// read positions strictly beyond those written) -> staging is out[4][3] only.
__device__ __forceinline__ u64 node_forward(const float* __restrict__ zin,
                                            const int* __restrict__ nbr_row,
                                            int lane,
                                            const ulonglong2 (*sw)[5][8]) {
    // 16 neighbor indices via broadcast int4 loads
    int4 i4[4];
#pragma unroll
    for (int q = 0; q < 4; q++) i4[q] = ((const int4*)nbr_row)[q];
    int idx[16] = {i4[0].x, i4[0].y, i4[0].z, i4[0].w,
                   i4[1].x, i4[1].y, i4[1].z, i4[1].w,
                   i4[2].x, i4[2].y, i4[2].z, i4[2].w,
                   i4[3].x, i4[3].y, i4[3].z, i4[3].w};

    // Gather burst: z is (N, B); one neighbor = 64 contiguous floats; lane reads its pair (LDG.64)
    u64 in[16];
#pragma unroll
    for (int j = 0; j < 16; j++)
        in[j] = *(const u64*)(zin + ((size_t)(unsigned)idx[j] << 6) + 2 * lane);

    u64 s[5][14];   // in-register sequence, overwritten in place layer by layer

    // ---- layer 0: 1 -> 5 channels, 16 -> 14 wide (weights in regs across all t) ----
#pragma unroll
    for (int co = 0; co < 5; co++) {
        ulonglong2 q0 = sw[0][co][0];   // (w0, w1)
        ulonglong2 q1 = sw[0][co][1];   // (w2, bias)
#pragma unroll
        for (int t = 0; t < 14; t++) {
            u64 acc = q1.y;
            acc = fma2(in[t],     q0.x, acc);
            acc = fma2(in[t + 1], q0.y, acc);
            acc = fma2(in[t + 2], q1.x, acc);
            s[co][t] = relu2(acc);
        }
    }

    // ---- layers 1..6: 5 -> 5 (or 1), in place, t-chunks of 3 ----
#pragma unroll
    for (int l = 1; l <= 6; l++) {
        const int Lo  = 14 - 2 * l;          // output length this layer
        const int nco = (l == 6) ? 1 : 5;
#pragma unroll
        for (int c0 = 0; c0 < Lo; c0 += 3) {
            const int CL = (Lo - c0 < 3) ? (Lo - c0) : 3;
            u64 out[4][3];                   // staging for co < nco-1 only
#pragma unroll
            for (int co = 0; co < 5; co++) {
                if (co < nco) {
                    const bool inplace = (co == nco - 1);
                    u64 acc[3];
                    {   // phase 1: bias + slots 8..14 (reads s[2],s[3],s[4])
                        ulonglong2 w4 = sw[l][co][4];
                        ulonglong2 w5 = sw[l][co][5];
                        ulonglong2 w6 = sw[l][co][6];
                        ulonglong2 w7 = sw[l][co][7];
#pragma unroll
                        for (int tt = 0; tt < CL; tt++) {
                            const int t = c0 + tt;
                            u64 a = w7.y;                       // bias (slot 15)
                            a = fma2(s[2][t + 2], w4.x, a);     // slot 8
                            a = fma2(s[3][t + 0], w4.y, a);     // slot 9
                            a = fma2(s[3][t + 1], w5.x, a);     // slot 10
                            a = fma2(s[3][t + 2], w5.y, a);     // slot 11
                            a = fma2(s[4][t + 0], w6.x, a);     // slot 12
                            a = fma2(s[4][t + 1], w6.y, a);     // slot 13
                            a = fma2(s[4][t + 2], w7.x, a);     // slot 14
                            acc[tt] = a;
                        }
                    }
                    {   // phase 2: slots 0..7 (reads s[0],s[1],s[2])
                        ulonglong2 w0 = sw[l][co][0];
                        ulonglong2 w1 = sw[l][co][1];
                        ulonglong2 w2 = sw[l][co][2];
                        ulonglong2 w3 = sw[l][co][3];
#pragma unroll
                        for (int tt = 0; tt < CL; tt++) {
                            const int t = c0 + tt;
                            u64 a = acc[tt];
                            a = fma2(s[0][t + 0], w0.x, a);     // slot 0
                            a = fma2(s[0][t + 1], w0.y, a);     // slot 1
                            a = fma2(s[0][t + 2], w1.x, a);     // slot 2
                            a = fma2(s[1][t + 0], w1.y, a);     // slot 3
                            a = fma2(s[1][t + 1], w2.x, a);     // slot 4
                            a = fma2(s[1][t + 2], w2.y, a);     // slot 5
                            a = fma2(s[2][t + 0], w3.x, a);     // slot 6
                            a = fma2(s[2][t + 1], w3.y, a);     // slot 7
                            u64 r = relu2(a);
                            if (inplace) s[co][t] = r;          // last co: in-place is safe
                            else         out[co][tt] = r;
                        }
                    }
                }
            }
            // writeback staged channels (next chunk reads positions >= c0+3 only)
#pragma unroll
            for (int co = 0; co < 4; co++)
                if (co < nco - 1)
#pragma unroll
                    for (int tt = 0; tt < CL; tt++)
                        s[co][c0 + tt] = out[co][tt];
        }
    }

    // layer-6 outputs sit at s[0][0], s[0][1]
    const u64 HALF2 = 0x3F0000003F000000ULL;  // {0.5f, 0.5f}
    return mul2(add2(s[0][0], s[0][1]), HALF2);
}

// ---------------- kernels ----------------
__global__ void __launch_bounds__(128) transpose_kernel(const float* __restrict__ x,
                                                        float* __restrict__ zt) {
    int n  = blockIdx.x * blockDim.x + threadIdx.x;
    int bp = blockIdx.y;  // batch pair 0..31
    if (n >= NN) return;
    float lo = x[(size_t)(2 * bp) * NN + n];
    float hi = x[(size_t)(2 * bp + 1) * NN + n];
    *(float2*)(zt + (size_t)n * BB + 2 * bp) = make_float2(lo, hi);
}

__global__ void clear_flags_kernel(unsigned char* f, int* cnt) {
    int i = blockIdx.x * blockDim.x + threadIdx.x;
    if (i < NN) f[i] = 0;
    if (i == 0) *cnt = 0;
}

__global__ void mark_flags_kernel(const int* __restrict__ drv,
                                  const int* __restrict__ nbr,
                                  unsigned char* f) {
    int i = blockIdx.x * blockDim.x + threadIdx.x;
    if (i < NDRVN * DD) {
        int d = drv[i >> 4];
        f[nbr[d * DD + (i & 15)]] = 1;
    }
}

__global__ void compact_kernel(const unsigned char* __restrict__ f,
                               int* __restrict__ list, int* __restrict__ cnt) {
    int i = blockIdx.x * blockDim.x + threadIdx.x;
    if (i < NN && f[i]) {
        int pos = atomicAdd(cnt, 1);
        list[pos] = i;
    }
}

// 64-thread blocks (2 warps = 2 nodes), 5 blocks/SM -> 204-reg budget, 10 warps/SM
__global__ void __launch_bounds__(64, 5) pass_kernel(const float* __restrict__ zin,
                                                     float* __restrict__ zout,
                                                     const int* __restrict__ nbr,
                                                     Params p) {
    __shared__ ulonglong2 s_w[7][5][8];
    load_weights(p, s_w);
    int warp = threadIdx.x >> 5;
    int lane = threadIdx.x & 31;
    int node = blockIdx.x * 2 + warp;
    if (node >= NN) return;
    u64 r = node_forward(zin, nbr + node * DD, lane, s_w);
    *(u64*)(zout + (size_t)node * BB + 2 * lane) = r;
}

__global__ void __launch_bounds__(64, 5) pass_list_kernel(const float* __restrict__ zin,
                                                          float* __restrict__ zout,
                                                          const int* __restrict__ nbr,
                                                          const int* __restrict__ list,
                                                          const int* __restrict__ cnt,
                                                          Params p) {
    __shared__ ulonglong2 s_w[7][5][8];
    load_weights(p, s_w);
    int warp = threadIdx.x >> 5;
    int lane = threadIdx.x & 31;
    int i = blockIdx.x * 2 + warp;
    if (i >= *cnt) return;
    int node = list[i];
    u64 r = node_forward(zin, nbr + node * DD, lane, s_w);
    *(u64*)(zout + (size_t)node * BB + 2 * lane) = r;
}

__global__ void __launch_bounds__(64, 5) driver_kernel(const float* __restrict__ zin,
                                                       const int* __restrict__ nbr,
                                                       const int* __restrict__ drv,
                                                       float* __restrict__ out,
                                                       Params p) {
    __shared__ ulonglong2 s_w[7][5][8];
    load_weights(p, s_w);
    int warp = threadIdx.x >> 5;
    int lane = threadIdx.x & 31;
    int i = blockIdx.x * 2 + warp;
    if (i >= NDRVN) return;
    int node = drv[i];
    u64 r = node_forward(zin, nbr + node * DD, lane, s_w);
    float lo, hi;
    asm("mov.b64 {%0, %1}, %2;" : "=f"(lo), "=f"(hi) : "l"(r));
    out[(size_t)(2 * lane) * NDRVN + i]     = lo;
    out[(size_t)(2 * lane + 1) * NDRVN + i] = hi;
}

// ---------------- launch ----------------
extern "C" void kernel_launch(void* const* d_in, const int* in_sizes, int n_in,
                              void* d_out, int out_size) {
    const float* x   = (const float*)d_in[0];
    const int*   nbr = (const int*)d_in[1];
    const int*   drv = (const int*)d_in[2];
    Params p;
    for (int l = 0; l < 7; l++) {
        p.w[l] = (const float*)d_in[3 + 2 * l];
        p.b[l] = (const float*)d_in[4 + 2 * l];
    }

    float* A; float* B; unsigned char* fl; int* lst; int* cnt;
    cudaGetSymbolAddress((void**)&A,   g_bufA);
    cudaGetSymbolAddress((void**)&B,   g_bufB);
    cudaGetSymbolAddress((void**)&fl,  g_flags);
    cudaGetSymbolAddress((void**)&lst, g_list);
    cudaGetSymbolAddress((void**)&cnt, g_cnt);

    const int blocks_full = (NN + 1) / 2;
    const int blocks_list = (MAXACT + 1) / 2;

    // transpose z0 to (N, B)
    transpose_kernel<<<dim3((NN + 127) / 128, BB / 2), 128>>>(x, A);
    // active-set flags for pass 3
    clear_flags_kernel<<<(NN + 255) / 256, 256>>>(fl, cnt);
    mark_flags_kernel<<<(NDRVN * DD + 255) / 256, 256>>>(drv, nbr, fl);
    // pass 1 (full)
    pass_kernel<<<blocks_full, 64>>>(A, B, nbr, p);
    // compact flags into list
    compact_kernel<<<(NN + 255) / 256, 256>>>(fl, lst, cnt);
    // pass 2 (full)
    pass_kernel<<<blocks_full, 64>>>(B, A, nbr, p);
    // pass 3 (compacted active set, <=16000 nodes)
    pass_list_kernel<<<blocks_list, 64>>>(A, B, nbr, lst, cnt, p);
    // pass 4 (drivers only, straight to output)
    driver_kernel<<<(NDRVN + 1) / 2, 64>>>(B, nbr, drv, (float*)d_out, p);
}

// round 15
// speedup vs baseline: 1.3285x; 1.3285x over previous
#include <cuda_runtime.h>
#include <cstdint>
#include <cstddef>

#define NN    50000
#define BB    64
#define DD    16
#define NDRVN 1000
#define MAXACT (NDRVN * DD)

typedef unsigned long long u64;

struct Params { const float* w[7]; const float* b[7]; };

// Scratch (static device arrays are the sanctioned workaround)
__device__ float g_bufA[(size_t)NN * BB];
__device__ float g_bufB[(size_t)NN * BB];
__device__ unsigned char g_flags[NN];
__device__ int g_list[MAXACT];
__device__ int g_cnt;

// ---------------- packed f32x2 primitives (Blackwell FFMA2 path) ----------------
__device__ __forceinline__ u64 fma2(u64 a, u64 b, u64 c) {
    u64 d;
    asm("fma.rn.f32x2 %0, %1, %2, %3;" : "=l"(d) : "l"(a), "l"(b), "l"(c));
    return d;
}
__device__ __forceinline__ u64 add2(u64 a, u64 b) {
    u64 d;
    asm("add.rn.f32x2 %0, %1, %2;" : "=l"(d) : "l"(a), "l"(b));
    return d;
}
__device__ __forceinline__ u64 mul2(u64 a, u64 b) {
    u64 d;
    asm("mul.rn.f32x2 %0, %1, %2;" : "=l"(d) : "l"(a), "l"(b));
    return d;
}
__device__ __forceinline__ u64 relu2(u64 x) {
    u64 r;
    asm("{\n\t"
        ".reg .f32 lo, hi;\n\t"
        "mov.b64 {lo, hi}, %1;\n\t"
        "max.f32 lo, lo, 0f00000000;\n\t"
        "max.f32 hi, hi, 0f00000000;\n\t"
        "mov.b64 %0, {lo, hi};\n\t"
        "}" : "=l"(r) : "l"(x));
    return r;
}

// ---------------- shared weights: duplicated (w,w) pairs, bias folded in ----------------
// s_w[l][co][q] as ulonglong2 (LDS.128 = 2 weight-pairs). Row of 16 duplicated floats:
//   layers 1..6: slots 0..14 = weights (ci*3+k), slot 15 = bias
//   layer  0   : slots 0..2  = weights, slot 3 = bias
__device__ __forceinline__ void load_weights(const Params& p, ulonglong2 (*sw)[5][8]) {
    float2* fp = (float2*)sw;
    for (int e = threadIdx.x; e < 7 * 5 * 16; e += blockDim.x) {
        int l = e / 80;
        int r = e % 80;
        int co = r / 16;
        int j  = r % 16;
        int nci   = (l == 0) ? 1 : 5;
        int nco   = (l == 6) ? 1 : 5;
        int nw    = nci * 3;
        int bslot = (l == 0) ? 3 : 15;
        float v = 0.0f;
        if (co < nco) {
            if (j < nw)          v = p.w[l][co * nw + j];
            else if (j == bslot) v = p.b[l][co];
        }
        fp[e] = make_float2(v, v);
    }
    __syncthreads();
}

// ---------------- layer-major streaming conv: one node per warp, batch-pair per lane ----
// R8 structure (CL=4, full staging) with ONE change: phase 1 of each inner-layer output
// is computed as 7 mul2 (rt=2, fma pipe) + add2 tree (alu pipe if FADD2 routes there),
// instead of a 7-FFMA2 chain (rt=3 from 3-distinct-u64-pair RF bank conflicts).
__device__ __forceinline__ u64 node_forward(const float* __restrict__ zin,
                                            const int* __restrict__ nbr_row,
                                            int lane,
                                            const ulonglong2 (*sw)[5][8]) {
    // 16 neighbor indices via broadcast int4 loads
    int4 i4[4];
#pragma unroll
    for (int q = 0; q < 4; q++) i4[q] = ((const int4*)nbr_row)[q];
    int idx[16] = {i4[0].x, i4[0].y, i4[0].z, i4[0].w,
                   i4[1].x, i4[1].y, i4[1].z, i4[1].w,
                   i4[2].x, i4[2].y, i4[2].z, i4[2].w,
                   i4[3].x, i4[3].y, i4[3].z, i4[3].w};

    // Gather burst: z is (N, B); one neighbor = 64 contiguous floats; lane reads its pair (LDG.64)
    u64 in[16];
#pragma unroll
    for (int j = 0; j < 16; j++)
        in[j] = *(const u64*)(zin + ((size_t)(unsigned)idx[j] << 6) + 2 * lane);

    u64 s[5][14];   // in-register sequence, overwritten in place layer by layer

    // ---- layer 0: 1 -> 5 channels, 16 -> 14 wide (weights in regs across all t) ----
#pragma unroll
    for (int co = 0; co < 5; co++) {
        ulonglong2 q0 = sw[0][co][0];   // (w0, w1)
        ulonglong2 q1 = sw[0][co][1];   // (w2, bias)
#pragma unroll
        for (int t = 0; t < 14; t++) {
            u64 acc = q1.y;
            acc = fma2(in[t],     q0.x, acc);
            acc = fma2(in[t + 1], q0.y, acc);
            acc = fma2(in[t + 2], q1.x, acc);
            s[co][t] = relu2(acc);
        }
    }

    // ---- layers 1..6: 5 -> 5 (or 1), in place, t-chunks of 4 ----
#pragma unroll
    for (int l = 1; l <= 6; l++) {
        const int Lo  = 14 - 2 * l;          // output length this layer
        const int nco = (l == 6) ? 1 : 5;
#pragma unroll
        for (int c0 = 0; c0 < Lo; c0 += 4) {
            const int CL = (Lo - c0 < 4) ? (Lo - c0) : 4;
            u64 out[5][4];
#pragma unroll
            for (int co = 0; co < 5; co++) {
                if (co < nco) {
                    u64 acc[4];
                    {   // phase 1: slots 8..14 + bias as mul2 products + add2 tree
                        ulonglong2 w4 = sw[l][co][4];
                        ulonglong2 w5 = sw[l][co][5];
                        ulonglong2 w6 = sw[l][co][6];
                        ulonglong2 w7 = sw[l][co][7];
#pragma unroll
                        for (int tt = 0; tt < CL; tt++) {
                            const int t = c0 + tt;
                            u64 m0 = mul2(s[2][t + 2], w4.x);   // slot 8
                            u64 m1 = mul2(s[3][t + 0], w4.y);   // slot 9
                            u64 m2 = mul2(s[3][t + 1], w5.x);   // slot 10
                            u64 m3 = mul2(s[3][t + 2], w5.y);   // slot 11
                            u64 m4 = mul2(s[4][t + 0], w6.x);   // slot 12
                            u64 m5 = mul2(s[4][t + 1], w6.y);   // slot 13
                            u64 m6 = mul2(s[4][t + 2], w7.x);   // slot 14
                            u64 a01 = add2(m0, m1);
                            u64 a23 = add2(m2, m3);
                            u64 a45 = add2(m4, m5);
                            u64 a6b = add2(m6, w7.y);           // + bias (slot 15)
                            acc[tt] = add2(add2(a01, a23), add2(a45, a6b));
                        }
                    }
                    {   // phase 2: slots 0..7 as FFMA2 chain onto acc
                        ulonglong2 w0 = sw[l][co][0];
                        ulonglong2 w1 = sw[l][co][1];
                        ulonglong2 w2 = sw[l][co][2];
                        ulonglong2 w3 = sw[l][co][3];
#pragma unroll
                        for (int tt = 0; tt < CL; tt++) {
                            const int t = c0 + tt;
                            u64 a = acc[tt];
                            a = fma2(s[0][t + 0], w0.x, a);     // slot 0
                            a = fma2(s[0][t + 1], w0.y, a);     // slot 1
                            a = fma2(s[0][t + 2], w1.x, a);     // slot 2
                            a = fma2(s[1][t + 0], w1.y, a);     // slot 3
                            a = fma2(s[1][t + 1], w2.x, a);     // slot 4
                            a = fma2(s[1][t + 2], w2.y, a);     // slot 5
                            a = fma2(s[2][t + 0], w3.x, a);     // slot 6
                            a = fma2(s[2][t + 1], w3.y, a);     // slot 7
                            out[co][tt] = relu2(a);
                        }
                    }
                }
            }
            // writeback after the full co sweep (next chunk reads positions >= c0+4 only)
#pragma unroll
            for (int co = 0; co < 5; co++)
                if (co < nco)
#pragma unroll
                    for (int tt = 0; tt < CL; tt++)
                        s[co][c0 + tt] = out[co][tt];
        }
    }

    // layer-6 outputs sit at s[0][0], s[0][1]
    const u64 HALF2 = 0x3F0000003F000000ULL;  // {0.5f, 0.5f}
    return mul2(add2(s[0][0], s[0][1]), HALF2);
}

// ---------------- kernels ----------------
__global__ void __launch_bounds__(128) transpose_kernel(const float* __restrict__ x,
                                                        float* __restrict__ zt) {
    int n  = blockIdx.x * blockDim.x + threadIdx.x;
    int bp = blockIdx.y;  // batch pair 0..31
    if (n >= NN) return;
    float lo = x[(size_t)(2 * bp) * NN + n];
    float hi = x[(size_t)(2 * bp + 1) * NN + n];
    *(float2*)(zt + (size_t)n * BB + 2 * bp) = make_float2(lo, hi);
}

__global__ void clear_flags_kernel(unsigned char* f, int* cnt) {
    int i = blockIdx.x * blockDim.x + threadIdx.x;
    if (i < NN) f[i] = 0;
    if (i == 0) *cnt = 0;
}

__global__ void mark_flags_kernel(const int* __restrict__ drv,
                                  const int* __restrict__ nbr,
                                  unsigned char* f) {
    int i = blockIdx.x * blockDim.x + threadIdx.x;
    if (i < NDRVN * DD) {
        int d = drv[i >> 4];
        f[nbr[d * DD + (i & 15)]] = 1;
    }
}

__global__ void compact_kernel(const unsigned char* __restrict__ f,
                               int* __restrict__ list, int* __restrict__ cnt) {
    int i = blockIdx.x * blockDim.x + threadIdx.x;
    if (i < NN && f[i]) {
        int pos = atomicAdd(cnt, 1);
        list[pos] = i;
    }
}

__global__ void __launch_bounds__(128) pass_kernel(const float* __restrict__ zin,
                                                   float* __restrict__ zout,
                                                   const int* __restrict__ nbr,
                                                   Params p) {
    __shared__ ulonglong2 s_w[7][5][8];
    load_weights(p, s_w);
    int warp = threadIdx.x >> 5;
    int lane = threadIdx.x & 31;
    int node = blockIdx.x * 4 + warp;
    if (node >= NN) return;
    u64 r = node_forward(zin, nbr + node * DD, lane, s_w);
    *(u64*)(zout + (size_t)node * BB + 2 * lane) = r;
}

__global__ void __launch_bounds__(128) pass_list_kernel(const float* __restrict__ zin,
                                                        float* __restrict__ zout,
                                                        const int* __restrict__ nbr,
                                                        const int* __restrict__ list,
                                                        const int* __restrict__ cnt,
                                                        Params p) {
    __shared__ ulonglong2 s_w[7][5][8];
    load_weights(p, s_w);
    int warp = threadIdx.x >> 5;
    int lane = threadIdx.x & 31;
    int i = blockIdx.x * 4 + warp;
    if (i >= *cnt) return;
    int node = list[i];
    u64 r = node_forward(zin, nbr + node * DD, lane, s_w);
    *(u64*)(zout + (size_t)node * BB + 2 * lane) = r;
}

__global__ void __launch_bounds__(128) driver_kernel(const float* __restrict__ zin,
                                                     const int* __restrict__ nbr,
                                                     const int* __restrict__ drv,
                                                     float* __restrict__ out,
                                                     Params p) {
    __shared__ ulonglong2 s_w[7][5][8];
    load_weights(p, s_w);
    int warp = threadIdx.x >> 5;
    int lane = threadIdx.x & 31;
    int i = blockIdx.x * 4 + warp;
    if (i >= NDRVN) return;
    int node = drv[i];
    u64 r = node_forward(zin, nbr + node * DD, lane, s_w);
    float lo, hi;
    asm("mov.b64 {%0, %1}, %2;" : "=f"(lo), "=f"(hi) : "l"(r));
    out[(size_t)(2 * lane) * NDRVN + i]     = lo;
    out[(size_t)(2 * lane + 1) * NDRVN + i] = hi;
}

// ---------------- launch ----------------
extern "C" void kernel_launch(void* const* d_in, const int* in_sizes, int n_in,
                              void* d_out, int out_size) {
    const float* x   = (const float*)d_in[0];
    const int*   nbr = (const int*)d_in[1];
    const int*   drv = (const int*)d_in[2];
    Params p;
    for (int l = 0; l < 7; l++) {
        p.w[l] = (const float*)d_in[3 + 2 * l];
        p.b[l] = (const float*)d_in[4 + 2 * l];
    }

    float* A; float* B; unsigned char* fl; int* lst; int* cnt;
    cudaGetSymbolAddress((void**)&A,   g_bufA);
    cudaGetSymbolAddress((void**)&B,   g_bufB);
    cudaGetSymbolAddress((void**)&fl,  g_flags);
    cudaGetSymbolAddress((void**)&lst, g_list);
    cudaGetSymbolAddress((void**)&cnt, g_cnt);

    const int blocks_full = (NN + 3) / 4;
    const int blocks_list = (MAXACT + 3) / 4;

    // transpose z0 to (N, B)
    transpose_kernel<<<dim3((NN + 127) / 128, BB / 2), 128>>>(x, A);
    // active-set flags for pass 3
    clear_flags_kernel<<<(NN + 255) / 256, 256>>>(fl, cnt);
    mark_flags_kernel<<<(NDRVN * DD + 255) / 256, 256>>>(drv, nbr, fl);
    // pass 1 (full)
    pass_kernel<<<blocks_full, 128>>>(A, B, nbr, p);
    // compact flags into list
    compact_kernel<<<(NN + 255) / 256, 256>>>(fl, lst, cnt);
    // pass 2 (full)
    pass_kernel<<<blocks_full, 128>>>(B, A, nbr, p);
    // pass 3 (compacted active set, <=16000 nodes)
    pass_list_kernel<<<blocks_list, 128>>>(A, B, nbr, lst, cnt, p);
    // pass 4 (drivers only, straight to output)
    driver_kernel<<<(NDRVN + 3) / 4, 128>>>(B, nbr, drv, (float*)d_out, p);
}